// round 2
// baseline (speedup 1.0000x reference)
#include <cuda_runtime.h>
#include <cuda_fp16.h>

#define NUM_POINTS 4
#define NUM_TABLES 10
#define TABLE_SIZE 35

// Per-lane LUT evaluation, all arithmetic in fp16 matching the jnp reference.
__device__ __forceinline__ float lane_eval(
    __half xh, int ci,
    const __half* __restrict__ s_cut,
    const __half* __restrict__ s_scale,
    const __half2* __restrict__ s_lut,
    __half c0h, __half clh, __half t0h, __half tLh)
{
    __half dval = __hsub(xh, s_cut[ci]);
    __half temp = __hmul(dval, s_scale[ci]);
    float tf = __half2float(temp);
    int idx = (int)tf;                        // temp >= 0 -> trunc == floor
    idx = max(0, min(idx, NUM_POINTS));       // defensive clamp
    if (ci == (NUM_TABLES - 1) && idx == 1) idx = 0;
    __half dec = __hsub(temp, __float2half((float)idx));
    int tbl = (ci == 0) ? idx : (1 + (ci - 1) * NUM_POINTS + idx);
    tbl = min(tbl, TABLE_SIZE - 1);           // defensive clamp (smem safety)
    __half2 p = s_lut[tbl];                   // {left_h, interval_h}
    // two separate roundings to match (left + interval*decimal) in jnp fp16
    __half y = __hadd(__low2half(p), __hmul(__high2half(p), dec));
    if (__hle(xh, c0h)) y = t0h;
    if (__hge(xh, clh)) y = tLh;
    return __half2float(y);
}

__global__ __launch_bounds__(256, 8)
void fplut_kernel(const float4* __restrict__ x4,
                  const void*  __restrict__ cut_raw,  // 11 entries, fp16 OR f32
                  const float* __restrict__ table,    // 35 f32
                  const float* __restrict__ scale,    // 10 f32
                  float4* __restrict__ out4,
                  int n4)
{
    __shared__ __half  s_cut[11];
    __shared__ __half  s_scale[10];
    __shared__ __half2 s_lut[35];   // {left_h, interval_h}

    int t = threadIdx.x;

    // dtype probe: if cut_points arrived as f32, first word is exactly -65504.0f.
    // If it's an fp16 array, the first 4 bytes decode to ~ -8704.0f.
    const float probe = ((const float*)cut_raw)[0];
    const bool cut_is_f32 = (probe < -60000.0f && probe > -70000.0f);

    if (t < 11) {
        s_cut[t] = cut_is_f32 ? __float2half(((const float*)cut_raw)[t])
                              : ((const __half*)cut_raw)[t];
    }
    if (t < 10) s_scale[t] = __float2half(scale[t]);
    if (t < 34) {
        __half lh = __float2half(table[t]);
        __half rh = __float2half(table[t + 1]);
        s_lut[t] = __halves2half2(lh, __hsub(rh, lh));
    }
    if (t == 34) s_lut[34] = __halves2half2(__float2half(table[34]), __float2half(0.f));
    __syncthreads();

    // uniform values in registers
    const float  c0f = __half2float(s_cut[0]);
    const float  clf = __half2float(s_cut[NUM_TABLES]);
    const __half c0h = s_cut[0];
    const __half clh = s_cut[NUM_TABLES];
    const __half t0h = __low2half(s_lut[0]);
    const __half tLh = __float2half(table[TABLE_SIZE - 1]);

    __half2 creg[NUM_TABLES - 1];
    #pragma unroll
    for (int k = 0; k < NUM_TABLES - 1; k++) creg[k] = __half2half2(s_cut[k + 1]);

    const int stride = gridDim.x * blockDim.x;
    for (int i = blockIdx.x * blockDim.x + t; i < n4; i += stride) {
        float4 v = x4[i];
        float xs[4] = {v.x, v.y, v.z, v.w};
        float ys[4];

        #pragma unroll
        for (int p = 0; p < 4; p += 2) {
            // clip in f32 (NaN flushes to c0 via fmaxf semantics -> y == table[0] == 0,
            // matching the reference's NaN->0 path: gelu(0) == 0 == table[0])
            float a = fminf(fmaxf(xs[p],     c0f), clf);
            float b = fminf(fmaxf(xs[p + 1], c0f), clf);
            __half2 xh2 = __floats2half2_rn(a, b);

            // searchsorted(side='right') via SIMD compare-count over interior cuts
            __half2 cnt = __float2half2_rn(0.f);
            #pragma unroll
            for (int k = 0; k < NUM_TABLES - 1; k++)
                cnt = __hadd2(cnt, __hge2(xh2, creg[k]));

            int ci0 = (int)__low2float(cnt);
            int ci1 = (int)__high2float(cnt);
            ci0 = max(0, min(ci0, NUM_TABLES - 1));
            ci1 = max(0, min(ci1, NUM_TABLES - 1));

            ys[p]     = lane_eval(__low2half(xh2),  ci0, s_cut, s_scale, s_lut,
                                  c0h, clh, t0h, tLh);
            ys[p + 1] = lane_eval(__high2half(xh2), ci1, s_cut, s_scale, s_lut,
                                  c0h, clh, t0h, tLh);
        }
        out4[i] = make_float4(ys[0], ys[1], ys[2], ys[3]);
    }
}

extern "C" void kernel_launch(void* const* d_in, const int* in_sizes, int n_in,
                              void* d_out, int out_size)
{
    const float* x     = (const float*)d_in[0];
    const void*  cut   = d_in[1];
    const float* table = (const float*)d_in[2];
    const float* scale = (const float*)d_in[3];
    float* out = (float*)d_out;

    int n  = in_sizes[0];
    int n4 = n / 4;                      // 67,108,864 / 4 = 16,777,216

    const int threads    = 256;
    const int per_thread = 8;            // 8 float4 per thread for MLP
    int blocks = (n4 + threads * per_thread - 1) / (threads * per_thread);

    fplut_kernel<<<blocks, threads>>>((const float4*)x, cut, table, scale,
                                      (float4*)out, n4);
}

// round 5
// speedup vs baseline: 1.0700x; 1.0700x over previous
#include <cuda_runtime.h>
#include <cuda_fp16.h>

#define NUM_POINTS 4
#define NUM_TABLES 10
#define TABLE_SIZE 35
#define LUT_N 65536

__device__ __half g_lut[LUT_N];

// ---------------------------------------------------------------------------
// Precompute: evaluate the exact reference fp16 chain for every fp16 pattern.
// ---------------------------------------------------------------------------
__global__ void build_lut_kernel(const void* __restrict__ cut_raw,
                                 const float* __restrict__ table,
                                 const float* __restrict__ scale)
{
    unsigned v = blockIdx.x * blockDim.x + threadIdx.x;
    if (v >= LUT_N) return;

    // dtype probe: f32 cut_points -> first word is exactly -65504.0f.
    const float probe = ((const float*)cut_raw)[0];
    const bool cut_is_f32 = (probe < -60000.0f && probe > -70000.0f);

    __half cut[NUM_TABLES + 1];
    #pragma unroll
    for (int i = 0; i <= NUM_TABLES; i++)
        cut[i] = cut_is_f32 ? __float2half(((const float*)cut_raw)[i])
                            : ((const __half*)cut_raw)[i];

    __half xh = __ushort_as_half((unsigned short)v);
    // reference NaN path: NaN -> 0
    if (__hisnan(xh)) xh = __float2half(0.0f);
    // clip (all finite fp16 already within [c0, cl] = [-65504, 65504], but
    // handle inf patterns so every LUT entry is well-defined)
    if (__hlt(xh, cut[0])) xh = cut[0];
    if (__hgt(xh, cut[NUM_TABLES])) xh = cut[NUM_TABLES];

    // searchsorted(side='right'), ci = clip(ss,1,10)-1
    int ci = 0;
    #pragma unroll
    for (int k = 1; k <= NUM_TABLES - 1; k++)
        if (__hge(xh, cut[k])) ci = k;

    __half dval = __hsub(xh, cut[ci]);
    __half temp = __hmul(dval, __float2half(scale[ci]));
    int idx = (int)__half2float(temp);            // temp >= 0 -> trunc == floor
    idx = max(0, min(idx, NUM_POINTS));
    if (ci == NUM_TABLES - 1 && idx == 1) idx = 0;
    __half dec = __hsub(temp, __float2half((float)idx));
    int tbl = (ci == 0) ? idx : (1 + (ci - 1) * NUM_POINTS + idx);
    tbl = min(tbl, TABLE_SIZE - 2);
    __half lh = __float2half(table[tbl]);
    __half rh = __float2half(table[tbl + 1]);
    // two separate fp16 roundings: left + interval*decimal
    __half y = __hadd(lh, __hmul(__hsub(rh, lh), dec));
    if (__hle(xh, cut[0])) y = __float2half(table[0]);
    if (__hge(xh, cut[NUM_TABLES])) y = __float2half(table[TABLE_SIZE - 1]);

    g_lut[v] = y;
}

// ---------------------------------------------------------------------------
// Main: stream f32 -> clip/cvt to fp16 bits -> smem LUT gather -> f32 out.
// ---------------------------------------------------------------------------
__global__ __launch_bounds__(1024, 1)
void fplut_main(const float4* __restrict__ x4,
                float4* __restrict__ out4,
                int n4,
                const float* __restrict__ x,
                float* __restrict__ out,
                int n,
                const void* __restrict__ cut_raw)
{
    extern __shared__ __half s_lut[];   // 65536 entries = 128 KB

    // stage LUT: 128 KB / 1024 threads = 8 x uint4 per thread
    {
        const uint4* src = (const uint4*)g_lut;
        uint4*       dst = (uint4*)s_lut;
        #pragma unroll
        for (int i = threadIdx.x; i < LUT_N * 2 / 16; i += 1024)
            dst[i] = src[i];
    }

    // clip constants (read once per thread; L1-broadcast, negligible)
    const float probe = ((const float*)cut_raw)[0];
    const bool cut_is_f32 = (probe < -60000.0f && probe > -70000.0f);
    __half c0h, clh;
    if (cut_is_f32) {
        c0h = __float2half(((const float*)cut_raw)[0]);
        clh = __float2half(((const float*)cut_raw)[NUM_TABLES]);
    } else {
        c0h = ((const __half*)cut_raw)[0];
        clh = ((const __half*)cut_raw)[NUM_TABLES];
    }
    const __half2 c0_2 = __half2half2(c0h);
    const __half2 cl_2 = __half2half2(clh);

    __syncthreads();

    const int stride = gridDim.x * blockDim.x;
    int i = blockIdx.x * blockDim.x + threadIdx.x;

    #pragma unroll 4
    for (; i < n4; i += stride) {
        float4 v = x4[i];
        // pack + clip in fp16 SIMD. NaN: hmax2 returns the non-NaN operand
        // -> index = bits(c0). Separately, raw NaN-pattern LUT entries hold
        // y(0); either path matches the reference's NaN handling.
        // f32 overflow: cvt gives +-inf, clipped here to cl/c0 (== reference).
        __half2 h01 = __hmin2(__hmax2(__floats2half2_rn(v.x, v.y), c0_2), cl_2);
        __half2 h23 = __hmin2(__hmax2(__floats2half2_rn(v.z, v.w), c0_2), cl_2);
        unsigned b01 = *reinterpret_cast<unsigned*>(&h01);
        unsigned b23 = *reinterpret_cast<unsigned*>(&h23);

        __half y0 = s_lut[b01 & 0xFFFFu];
        __half y1 = s_lut[b01 >> 16];
        __half y2 = s_lut[b23 & 0xFFFFu];
        __half y3 = s_lut[b23 >> 16];

        out4[i] = make_float4(__half2float(y0), __half2float(y1),
                              __half2float(y2), __half2float(y3));
    }

    // scalar tail (n not multiple of 4); no-op for this problem's shapes
    for (int j = n4 * 4 + blockIdx.x * blockDim.x + threadIdx.x; j < n;
         j += stride) {
        __half xh = __float2half(fminf(fmaxf(x[j], __half2float(c0h)),
                                       __half2float(clh)));
        out[j] = __half2float(s_lut[(unsigned)__half_as_ushort(xh)]);
    }
}

extern "C" void kernel_launch(void* const* d_in, const int* in_sizes, int n_in,
                              void* d_out, int out_size)
{
    const float* x     = (const float*)d_in[0];
    const void*  cut   = d_in[1];
    const float* table = (const float*)d_in[2];
    const float* scale = (const float*)d_in[3];
    float* out = (float*)d_out;

    int n  = in_sizes[0];
    int n4 = n / 4;

    int sms = 148;
    cudaDeviceGetAttribute(&sms, cudaDevAttrMultiProcessorCount, 0);

    cudaFuncSetAttribute(fplut_main,
                         cudaFuncAttributeMaxDynamicSharedMemorySize,
                         LUT_N * (int)sizeof(__half));

    build_lut_kernel<<<LUT_N / 1024, 1024>>>(cut, table, scale);
    fplut_main<<<sms, 1024, LUT_N * (int)sizeof(__half)>>>(
        (const float4*)x, (float4*)out, n4, x, out, n, cut);
}

// round 7
// speedup vs baseline: 1.1642x; 1.0881x over previous
#include <cuda_runtime.h>
#include <cuda_fp16.h>

#define NUM_POINTS 4
#define NUM_TABLES 10
#define TABLE_SIZE 35
#define LUT_N 65536

__device__ __half g_lut[LUT_N];

// ---------------------------------------------------------------------------
// Precompute: evaluate the exact reference fp16 chain for every fp16 pattern.
// ---------------------------------------------------------------------------
__global__ void build_lut_kernel(const void* __restrict__ cut_raw,
                                 const float* __restrict__ table,
                                 const float* __restrict__ scale)
{
    unsigned v = blockIdx.x * blockDim.x + threadIdx.x;
    if (v >= LUT_N) return;

    // dtype probe: f32 cut_points -> first word is exactly -65504.0f.
    const float probe = ((const float*)cut_raw)[0];
    const bool cut_is_f32 = (probe < -60000.0f && probe > -70000.0f);

    __half cut[NUM_TABLES + 1];
    #pragma unroll
    for (int i = 0; i <= NUM_TABLES; i++)
        cut[i] = cut_is_f32 ? __float2half(((const float*)cut_raw)[i])
                            : ((const __half*)cut_raw)[i];

    __half xh = __ushort_as_half((unsigned short)v);
    if (__hisnan(xh)) xh = __float2half(0.0f);          // reference NaN -> 0
    if (__hlt(xh, cut[0])) xh = cut[0];
    if (__hgt(xh, cut[NUM_TABLES])) xh = cut[NUM_TABLES];

    // searchsorted(side='right'), ci = clip(ss,1,10)-1
    int ci = 0;
    #pragma unroll
    for (int k = 1; k <= NUM_TABLES - 1; k++)
        if (__hge(xh, cut[k])) ci = k;

    __half dval = __hsub(xh, cut[ci]);
    __half temp = __hmul(dval, __float2half(scale[ci]));
    int idx = (int)__half2float(temp);                  // temp >= 0 -> trunc == floor
    idx = max(0, min(idx, NUM_POINTS));
    if (ci == NUM_TABLES - 1 && idx == 1) idx = 0;
    __half dec = __hsub(temp, __float2half((float)idx));
    int tbl = (ci == 0) ? idx : (1 + (ci - 1) * NUM_POINTS + idx);
    tbl = min(tbl, TABLE_SIZE - 2);
    __half lh = __float2half(table[tbl]);
    __half rh = __float2half(table[tbl + 1]);
    __half y = __hadd(lh, __hmul(__hsub(rh, lh), dec)); // two fp16 roundings
    if (__hle(xh, cut[0])) y = __float2half(table[0]);
    if (__hge(xh, cut[NUM_TABLES])) y = __float2half(table[TABLE_SIZE - 1]);

    g_lut[v] = y;
}

// ---------------------------------------------------------------------------
// Main: stream f32 -> clip/cvt to fp16 bits -> smem LUT gather -> f32 out.
// Batch-of-4 structure: 4 independent LDG.128 issued before any consume,
// so each warp keeps 4 loads in flight (MLP_p1 = 4).
// ---------------------------------------------------------------------------
__global__ __launch_bounds__(1024, 1)
void fplut_main(const float4* __restrict__ x4,
                float4* __restrict__ out4,
                int n4,
                const float* __restrict__ x,
                float* __restrict__ out,
                int n,
                const void* __restrict__ cut_raw)
{
    extern __shared__ __half s_lut[];   // 65536 entries = 128 KB

    // stage LUT: 128 KB / 1024 threads = 8 x uint4 per thread
    {
        const uint4* src = (const uint4*)g_lut;
        uint4*       dst = (uint4*)s_lut;
        #pragma unroll
        for (int i = threadIdx.x; i < LUT_N * 2 / 16; i += 1024)
            dst[i] = src[i];
    }

    const float probe = ((const float*)cut_raw)[0];
    const bool cut_is_f32 = (probe < -60000.0f && probe > -70000.0f);
    __half c0h, clh;
    if (cut_is_f32) {
        c0h = __float2half(((const float*)cut_raw)[0]);
        clh = __float2half(((const float*)cut_raw)[NUM_TABLES]);
    } else {
        c0h = ((const __half*)cut_raw)[0];
        clh = ((const __half*)cut_raw)[NUM_TABLES];
    }
    const __half2 c0_2 = __half2half2(c0h);
    const __half2 cl_2 = __half2half2(clh);

    __syncthreads();

    const int stride = gridDim.x * blockDim.x;
    int i = blockIdx.x * blockDim.x + threadIdx.x;

    // main batched loop: 4 independent loads in flight per warp
    for (; i + 3 * stride < n4; i += 4 * stride) {
        float4 v0 = x4[i];
        float4 v1 = x4[i + stride];
        float4 v2 = x4[i + 2 * stride];
        float4 v3 = x4[i + 3 * stride];

        float4 r[4];
        const float4 vv[4] = {v0, v1, v2, v3};
        #pragma unroll
        for (int b = 0; b < 4; b++) {
            // pack + clip in fp16 SIMD. NaN -> c0 index (LUT[c0]=table[0]=y(0)
            // matches reference NaN->0). f32 overflow -> inf -> clipped here.
            __half2 h01 = __hmin2(__hmax2(__floats2half2_rn(vv[b].x, vv[b].y), c0_2), cl_2);
            __half2 h23 = __hmin2(__hmax2(__floats2half2_rn(vv[b].z, vv[b].w), c0_2), cl_2);
            unsigned b01 = *reinterpret_cast<const unsigned*>(&h01);
            unsigned b23 = *reinterpret_cast<const unsigned*>(&h23);
            r[b] = make_float4(__half2float(s_lut[b01 & 0xFFFFu]),
                               __half2float(s_lut[b01 >> 16]),
                               __half2float(s_lut[b23 & 0xFFFFu]),
                               __half2float(s_lut[b23 >> 16]));
        }

        out4[i]              = r[0];
        out4[i + stride]     = r[1];
        out4[i + 2 * stride] = r[2];
        out4[i + 3 * stride] = r[3];
    }

    // remainder (0..3 iterations per thread)
    for (; i < n4; i += stride) {
        float4 v = x4[i];
        __half2 h01 = __hmin2(__hmax2(__floats2half2_rn(v.x, v.y), c0_2), cl_2);
        __half2 h23 = __hmin2(__hmax2(__floats2half2_rn(v.z, v.w), c0_2), cl_2);
        unsigned b01 = *reinterpret_cast<const unsigned*>(&h01);
        unsigned b23 = *reinterpret_cast<const unsigned*>(&h23);
        out4[i] = make_float4(__half2float(s_lut[b01 & 0xFFFFu]),
                              __half2float(s_lut[b01 >> 16]),
                              __half2float(s_lut[b23 & 0xFFFFu]),
                              __half2float(s_lut[b23 >> 16]));
    }

    // scalar tail (n not multiple of 4); no-op for this problem's shapes
    for (int j = n4 * 4 + blockIdx.x * blockDim.x + threadIdx.x; j < n;
         j += stride) {
        __half xh = __float2half(fminf(fmaxf(x[j], __half2float(c0h)),
                                       __half2float(clh)));
        out[j] = __half2float(s_lut[(unsigned)__half_as_ushort(xh)]);
    }
}

extern "C" void kernel_launch(void* const* d_in, const int* in_sizes, int n_in,
                              void* d_out, int out_size)
{
    const float* x     = (const float*)d_in[0];
    const void*  cut   = d_in[1];
    const float* table = (const float*)d_in[2];
    const float* scale = (const float*)d_in[3];
    float* out = (float*)d_out;

    int n  = in_sizes[0];
    int n4 = n / 4;

    int sms = 148;
    cudaDeviceGetAttribute(&sms, cudaDevAttrMultiProcessorCount, 0);

    cudaFuncSetAttribute(fplut_main,
                         cudaFuncAttributeMaxDynamicSharedMemorySize,
                         LUT_N * (int)sizeof(__half));

    build_lut_kernel<<<LUT_N / 1024, 1024>>>(cut, table, scale);
    fplut_main<<<sms, 1024, LUT_N * (int)sizeof(__half)>>>(
        (const float4*)x, (float4*)out, n4, x, out, n, cut);
}